// round 16
// baseline (speedup 1.0000x reference)
#include <cuda_runtime.h>
#include <cuda.h>
#include <cstdint>

// Problem constants
static constexpr int Lc  = 32;
static constexpr int Kc  = 4;
static constexpr int Dc  = 1024;
static constexpr int QOc = 1024;
static constexpr int KVc = 256;
static constexpr int FFc = 2816;

typedef unsigned long long ull;

// Scratch partials (device globals): summed over col-slices by reduce_out.
__device__ float scratchM[32 * 4 * 12 * 1024];   // [l][cs(4)][v(12)][d]
__device__ float scratchQ[32 * 2 * 4 * 1024];    // [l][cs(2)][k][d]
__device__ float scratchO[32 * 2 * 4 * 1024];

// Shared memory layout (bytes), 256-thr CTA:
//   [0, 131072)        8 warps x 2 slots x 8192 (TMA weight tiles, SW128)
//   [131072, 164864)   cursed slice (max 12 x 704 floats)
//   [164864, +128)     16 mbarriers (8 warps x 2 slots)
static constexpr int SLOT_B   = 8192;
static constexpr int WSLOTS_B = 8 * 2 * SLOT_B;        // 131072
static constexpr int CUR_OFF  = WSLOTS_B;
static constexpr int MBAR_OFF = WSLOTS_B + 12 * 704 * 4;   // 164864
static constexpr int SMEM_B   = MBAR_OFF + 128;            // 164992

// ---------------- f32x2 packed FMA (sm_103a) ----------------
__device__ __forceinline__ void fma2(ull& acc, ull a, ull b) {
    asm("fma.rn.f32x2 %0, %1, %2, %0;" : "+l"(acc) : "l"(a), "l"(b));
}
__device__ __forceinline__ float hsum2(ull v) {
    return __uint_as_float((uint32_t)v) + __uint_as_float((uint32_t)(v >> 32));
}

// ---------------- cp.async (cursed staging only) ----------------
__device__ __forceinline__ void cp_async16(uint32_t saddr, const void* gptr) {
    asm volatile("cp.async.cg.shared.global [%0], [%1], 16;" :: "r"(saddr), "l"(gptr));
}
__device__ __forceinline__ void cp_commit() {
    asm volatile("cp.async.commit_group;");
}
__device__ __forceinline__ void cp_wait0() {
    asm volatile("cp.async.wait_group 0;");
}

// ---------------- mbarrier + TMA ----------------
__device__ __forceinline__ void mbar_init(uint32_t a) {
    asm volatile("mbarrier.init.shared.b64 [%0], 1;" :: "r"(a) : "memory");
}
__device__ __forceinline__ void mbar_expect(uint32_t a, uint32_t bytes) {
    asm volatile("mbarrier.arrive.expect_tx.shared.b64 _, [%0], %1;"
                 :: "r"(a), "r"(bytes) : "memory");
}
__device__ __forceinline__ void mbar_wait(uint32_t a, int ph) {
    asm volatile(
        "{\n\t.reg .pred P;\n\t"
        "WL%=:\n\t"
        "mbarrier.try_wait.parity.acquire.cta.shared::cta.b64 P, [%0], %1, 0x989680;\n\t"
        "@P bra WD%=;\n\t"
        "bra WL%=;\n\t"
        "WD%=:\n\t}"
        :: "r"(a), "r"(ph) : "memory");
}
__device__ __forceinline__ void tma2d(uint32_t dst, const CUtensorMap* m,
                                      int x, int y, uint32_t mbar) {
    asm volatile(
        "cp.async.bulk.tensor.2d.shared::cta.global.tile.mbarrier::complete_tx::bytes "
        "[%0], [%1, {%2, %3}], [%4];"
        :: "r"(dst), "l"(m), "r"(x), "r"(y), "r"(mbar) : "memory");
}

// =====================================================================
// run_tma: warp-private streaming over NT tiles of 32 cols x 64 rows.
// Lane owns rows lane and lane+32 of the tile (acc[M] each). Per j-step,
// all lanes use logical quad j; SW128 maps to distinct physical quads
// (conflict-free). Cursed quads read as true broadcasts from the CTA
// cursed slice. 2-slot TMA ring, warp-private mbarriers, no CTA sync.
// =====================================================================
template<int M>
__device__ __forceinline__ void run_tma(const CUtensorMap* tmap,
                                        int x0, int y0, int NT, int slice,
                                        char* smemc, int lane, int warp,
                                        float* base)
{
    char* slots = smemc + warp * 2 * SLOT_B;
    const uint32_t slot0 = (uint32_t)__cvta_generic_to_shared(slots);
    const uint32_t mb0   = (uint32_t)__cvta_generic_to_shared(smemc + MBAR_OFF)
                           + (uint32_t)warp * 16;
    const float* cur = (const float*)(smemc + CUR_OFF);

    ull accA[M], accB[M];
#pragma unroll
    for (int v = 0; v < M; ++v) { accA[v] = 0ull; accB[v] = 0ull; }

    if (lane == 0) {
        mbar_expect(mb0, SLOT_B);
        tma2d(slot0, tmap, x0, y0, mb0);
        mbar_expect(mb0 + 8, SLOT_B);
        tma2d(slot0 + SLOT_B, tmap, x0 + 32, y0, mb0 + 8);
    }

    const int sw = (lane & 7) << 4;       // SW128 physical-quad XOR for this row
    for (int t = 0; t < NT; ++t) {
        const int s  = t & 1;
        const int ph = (t >> 1) & 1;
        mbar_wait(mb0 + s * 8, ph);

        const char* sp = slots + s * SLOT_B;
        const char* wA = sp + lane * 128;
        const char* wB = sp + (lane + 32) * 128;
        const float* cb = cur + t * 32;

#pragma unroll
        for (int j = 0; j < 8; ++j) {
            const int q = (j << 4) ^ sw;
            const double2 a = *(const double2*)(wA + q);
            const double2 b = *(const double2*)(wB + q);
            const ull a01 = __double_as_longlong(a.x), a23 = __double_as_longlong(a.y);
            const ull b01 = __double_as_longlong(b.x), b23 = __double_as_longlong(b.y);
#pragma unroll
            for (int v = 0; v < M; ++v) {
                const double2 c = *(const double2*)(cb + v * slice + j * 4);
                const ull c01 = __double_as_longlong(c.x);
                const ull c23 = __double_as_longlong(c.y);
                fma2(accA[v], a01, c01); fma2(accA[v], a23, c23);
                fma2(accB[v], b01, c01); fma2(accB[v], b23, c23);
            }
        }

        // Re-arm this slot for tile t+2 (this warp's reads of slot s are done).
        if (t + 2 < NT) {
            __syncwarp();
            if (lane == 0) {
                mbar_expect(mb0 + s * 8, SLOT_B);
                tma2d(slot0 + s * SLOT_B, tmap, x0 + (t + 2) * 32, y0, mb0 + s * 8);
            }
        }
    }

#pragma unroll
    for (int v = 0; v < M; ++v) {
        base[v * 1024 + lane]      = hsum2(accA[v]);
        base[v * 1024 + 32 + lane] = hsum2(accB[v]);
    }
}

// =====================================================================
// Kernel A. Blocks:
//   [0,256)   MLP: l(32) x cs(4: 704-col slices) x rb(2: 512-row blocks)
//   [256,384) Q:   l x cs(2: 512) x rb(2)
//   [384,512) O    [512,576) K: l x rb   [576,640) V
//   [640,696) residual copy
// Each of 8 warps owns 64 rows. KV writes out directly; MLP/Q/O write
// per-slice partials to scratch.
// =====================================================================
extern "C" __global__ void __launch_bounds__(256)
proj_tma(const float* __restrict__ residual,
         const float* __restrict__ cq, const float* __restrict__ ck,
         const float* __restrict__ cv, const float* __restrict__ co,
         const float* __restrict__ cm,
         float* __restrict__ out,
         const __grid_constant__ CUtensorMap tWd,
         const __grid_constant__ CUtensorMap tWq,
         const __grid_constant__ CUtensorMap tWo,
         const __grid_constant__ CUtensorMap tWk,
         const __grid_constant__ CUtensorMap tWv)
{
    extern __shared__ __align__(128) char smemc[];

    const int b = blockIdx.x;
    if (b >= 640) {                       // residual copy (s=0 rows)
        const float4* r4 = reinterpret_cast<const float4*>(residual);
        float4* o4 = reinterpret_cast<float4*>(out);
        const int i0 = (b - 640) * 4096 + (int)threadIdx.x;
#pragma unroll
        for (int j = 0; j < 16; ++j) {
            const int i = i0 + j * 256;   // < 229376
            const int chunk  = i >> 10;
            const int within = i & 1023;
            o4[(size_t)chunk * 2048 + within] = r4[i];
        }
        return;
    }

    const int tid  = threadIdx.x;
    const int lane = tid & 31;
    const int warp = tid >> 5;

    // ---- decode ----
    const CUtensorMap* tmap;
    const float* C;        // cursed slice base (vec0, col0 of slice)
    int I, slice, NT, M, x0, y0, l, rb;
    float* base;

    if (b < 256) {                                    // MLP
        l = b >> 3; const int cs = (b >> 1) & 3; rb = b & 1;
        tmap = &tWd; I = FFc; slice = 704; NT = 22; M = 12;
        C = cm + (size_t)l * 12 * FFc + cs * 704;
        x0 = cs * 704;
        base = scratchM + (size_t)(l * 4 + cs) * 12 * 1024 + rb * 512 + warp * 64;
    } else if (b < 512) {                             // Q / O
        int t = b - 256;
        const bool isO = t >= 128; if (isO) t -= 128;
        l = t >> 2; const int cs = (t >> 1) & 1; rb = t & 1;
        tmap = isO ? &tWo : &tWq; I = QOc; slice = 512; NT = 16; M = 4;
        C = (isO ? co : cq) + (size_t)l * 4 * QOc + cs * 512;
        x0 = cs * 512;
        base = (isO ? scratchO : scratchQ)
               + (size_t)(l * 2 + cs) * 4 * 1024 + rb * 512 + warp * 64;
    } else {                                          // K / V -> direct out
        int t = b - 512;
        const bool isV = t >= 64; if (isV) t -= 64;
        l = t >> 1; rb = t & 1;
        tmap = isV ? &tWv : &tWk; I = KVc; slice = 256; NT = 8; M = 4;
        C = (isV ? cv : ck) + (size_t)l * 4 * KVc;
        x0 = 0;
        const int m = isV ? 2 : 1;
        base = out + (size_t)(l * 56 + m * 8 + 4) * 1024 + rb * 512 + warp * 64;
    }
    y0 = l * 1024 + rb * 512 + warp * 64;

    // ---- init mbarriers + stage cursed slice (once per CTA) ----
    if (tid < 16)
        mbar_init((uint32_t)__cvta_generic_to_shared(smemc + MBAR_OFF) + tid * 8);

    const uint32_t curs = (uint32_t)__cvta_generic_to_shared(smemc + CUR_OFF);
    const int s4 = slice / 4;
    for (int i = tid; i < M * s4; i += 256) {
        const int v = i / s4, c = i - v * s4;
        cp_async16(curs + (uint32_t)(v * slice + c * 4) * 4u,
                   C + (size_t)v * I + c * 4);
    }
    cp_commit(); cp_wait0();
    __syncthreads();

    if (b < 256) run_tma<12>(tmap, x0, y0, NT, slice, smemc, lane, warp, base);
    else         run_tma<4>(tmap, x0, y0, NT, slice, smemc, lane, warp, base);
}

// =====================================================================
// Kernel B: sum slice partials, write outputs, residual-independent.
//   [0,393216) MLP (4 partials)  [393216,524288) Q (2)  [524288,655360) O (2)
// =====================================================================
extern "C" __global__ void __launch_bounds__(256)
reduce_out(float* __restrict__ out)
{
    const int x = blockIdx.x * 256 + threadIdx.x;

    if (x < 393216) {                       // MLP
        const int d = x & 1023;
        int t = x >> 10;
        const int v = t % 12, l = t / 12;
        const float* p = scratchM + ((size_t)l * 48 + v) * 1024 + d;
        float s = 0.f;
#pragma unroll
        for (int cs = 0; cs < 4; ++cs) s += p[(size_t)cs * 12 * 1024];
        const int mi = v >> 2;
        const int m  = (mi == 2) ? 6 : (3 + mi);
        const int k  = v & 3;
        out[(size_t)(l * 56 + m * 8 + 4 + k) * 1024 + d] = s;
    } else if (x < 524288) {                // Q (m=0)
        const int y = x - 393216;
        const int d = y & 1023;
        int t = y >> 10;
        const int k = t & 3, l = t >> 2;
        const float* p = scratchQ + ((size_t)l * 8 + k) * 1024 + d;
        const float s = p[0] + p[4 * 1024];
        out[(size_t)(l * 56 + 0 * 8 + 4 + k) * 1024 + d] = s;
    } else if (x < 655360) {                // O (m=5)
        const int y = x - 524288;
        const int d = y & 1023;
        int t = y >> 10;
        const int k = t & 3, l = t >> 2;
        const float* p = scratchO + ((size_t)l * 8 + k) * 1024 + d;
        const float s = p[0] + p[4 * 1024];
        out[(size_t)(l * 56 + 5 * 8 + 4 + k) * 1024 + d] = s;
    }
}

// ---------------- host side ----------------
typedef CUresult (*PFN_encTiled)(CUtensorMap*, CUtensorMapDataType, cuuint32_t,
    void*, const cuuint64_t*, const cuuint64_t*, const cuuint32_t*,
    const cuuint32_t*, CUtensorMapInterleave, CUtensorMapSwizzle,
    CUtensorMapL2promotion, CUtensorMapFloatOOBfill);

static PFN_encTiled get_enc() {
    static PFN_encTiled fn = nullptr;
    if (!fn) {
        cudaDriverEntryPointQueryResult qr;
        void* p = nullptr;
        cudaGetDriverEntryPointByVersion("cuTensorMapEncodeTiled", &p, 12000,
                                         cudaEnableDefault, &qr);
        fn = (PFN_encTiled)p;
    }
    return fn;
}

static void enc_w(CUtensorMap* m, const void* ptr, uint64_t cols) {
    cuuint64_t gd[2] = {cols, 32768};         // [I, L*D]
    cuuint64_t gs[1] = {cols * 4};
    cuuint32_t bd[2] = {32, 64};              // 128B x 64 rows (SW128)
    cuuint32_t es[2] = {1, 1};
    get_enc()(m, CU_TENSOR_MAP_DATA_TYPE_FLOAT32, 2, (void*)ptr, gd, gs, bd, es,
              CU_TENSOR_MAP_INTERLEAVE_NONE, CU_TENSOR_MAP_SWIZZLE_128B,
              CU_TENSOR_MAP_L2_PROMOTION_L2_128B,
              CU_TENSOR_MAP_FLOAT_OOB_FILL_NONE);
}

extern "C" void kernel_launch(void* const* d_in, const int* in_sizes, int n_in,
                              void* d_out, int out_size)
{
    const float* residual = (const float*)d_in[0];
    const float* cq       = (const float*)d_in[1];
    const float* ck       = (const float*)d_in[2];
    const float* cv       = (const float*)d_in[3];
    const float* co       = (const float*)d_in[4];
    const float* cm       = (const float*)d_in[5];
    const float* Wq       = (const float*)d_in[6];
    const float* Wk       = (const float*)d_in[7];
    const float* Wv       = (const float*)d_in[8];
    const float* Wo       = (const float*)d_in[9];
    const float* Wd       = (const float*)d_in[10];
    float* out            = (float*)d_out;

    static bool attr_set = false;
    if (!attr_set) {
        cudaFuncSetAttribute(proj_tma,
                             cudaFuncAttributeMaxDynamicSharedMemorySize, SMEM_B);
        attr_set = true;
    }

    CUtensorMap tWd, tWq, tWo, tWk, tWv;
    enc_w(&tWd, Wd, FFc);
    enc_w(&tWq, Wq, QOc);
    enc_w(&tWo, Wo, QOc);
    enc_w(&tWk, Wk, KVc);
    enc_w(&tWv, Wv, KVc);

    proj_tma<<<696, 256, SMEM_B>>>(residual, cq, ck, cv, co, cm, out,
                                   tWd, tWq, tWo, tWk, tWv);
    reduce_out<<<2560, 256>>>(out);
}